// round 7
// baseline (speedup 1.0000x reference)
#include <cuda_runtime.h>
#include <math.h>

#define Hn     8
#define Nn     512
#define Dn     64
#define DNn    128
#define DEn    64
#define INNERn 512

typedef unsigned long long ull;

__device__ __forceinline__ ull pk2(float lo, float hi) {
    ull r; asm("mov.b64 %0,{%1,%2};" : "=l"(r) : "f"(lo), "f"(hi)); return r;
}
__device__ __forceinline__ float2 upk2(ull v) {
    float2 r; asm("mov.b64 {%0,%1},%2;" : "=f"(r.x), "=f"(r.y) : "l"(v)); return r;
}
__device__ __forceinline__ void fma2(ull& d, ull a, ull b) {
    asm("fma.rn.f32x2 %0,%1,%2,%3;" : "=l"(d) : "l"(a), "l"(b), "l"(d));
}
__device__ __forceinline__ void add2(ull& d, ull a) {
    asm("add.rn.f32x2 %0,%1,%2;" : "=l"(d) : "l"(d), "l"(a));
}

// ---------------- scratch ----------------
__device__ float g_q  [Hn * Nn * Dn];
__device__ float g_k  [Hn * Nn * Dn];
__device__ float g_v  [Hn * Nn * Dn];
__device__ float g_qe [Hn * Nn * DEn];
__device__ float g_qbe[Hn * Nn];
__device__ float g_sim[Hn * Nn * Nn];    // qk logits, then unnormalized p
__device__ float g_sinv[Hn * Nn];
__device__ float g_ew [Hn * Nn * DEn];   // normalized
__device__ float g_M  [INNERn * DNn];
__device__ float g_VW [Hn * Nn * DNn];   // VW[h*512+j][o] = (V_h @ Wo_h)[j][o]
__device__ float g_bvec[DNn];

// ---------------- kernel 1: QKV projection (+ fused qe, qbe) --------
__global__ void __launch_bounds__(256)
qkv_kernel(const float* __restrict__ nodes,
           const float* __restrict__ Wq, const float* __restrict__ bq,
           const float* __restrict__ Wk, const float* __restrict__ bk,
           const float* __restrict__ Wv, const float* __restrict__ bv,
           const float* __restrict__ We, const float* __restrict__ be)
{
    __shared__ float sN[32][DNn];
    __shared__ float sW[DNn][64];

    const int it = blockIdx.x;
    const int ct = blockIdx.y;
    const int mat = ct >> 3;
    const int h   = ct & 7;
    const int colbase = h * 64;
    const float* W    = (mat == 0) ? Wq : (mat == 1 ? Wk : Wv);
    const float* bias = (mat == 0) ? bq : (mat == 1 ? bk : bv);
    float* out        = (mat == 0) ? g_q : (mat == 1 ? g_k : g_v);

    const int i0 = it * 32;
    const int t  = threadIdx.x;

    {
        const float4* nf = (const float4*)(nodes + (size_t)i0 * DNn);
        float4* sNf = (float4*)&sN[0][0];
        #pragma unroll
        for (int r = 0; r < 4; r++) sNf[t + 256 * r] = nf[t + 256 * r];
    }
    #pragma unroll
    for (int r = 0; r < 8; r++) {
        int idx = t + 256 * r;
        int f = idx >> 4, c4 = idx & 15;
        ((float4*)&sW[f][0])[c4] = *(const float4*)(W + (size_t)f * INNERn + colbase + c4 * 4);
    }
    __syncthreads();

    const int col   = t & 63;
    const int ibase = t >> 6;
    float acc[8];
    #pragma unroll
    for (int r = 0; r < 8; r++) acc[r] = 0.f;

    for (int f = 0; f < DNn; f++) {
        float w = sW[f][col];
        #pragma unroll
        for (int r = 0; r < 8; r++) acc[r] += sN[ibase + 4 * r][f] * w;
    }

    const float b  = bias[colbase + col];
    const float sc = (mat == 0) ? 0.125f : 1.0f;
    float vals[8];
    #pragma unroll
    for (int r = 0; r < 8; r++) {
        vals[r] = (acc[r] + b) * sc;
        int i = i0 + ibase + 4 * r;
        out[(size_t)h * (Nn * Dn) + (size_t)i * Dn + col] = vals[r];
    }

    if (mat == 0) {
        float (*sOut)[Dn] = (float(*)[Dn])&sW[0][0];
        __syncthreads();
        #pragma unroll
        for (int r = 0; r < 8; r++) sOut[ibase + 4 * r][col] = vals[r];
        __syncthreads();

        float wreg[Dn];
        #pragma unroll
        for (int d = 0; d < Dn; d++) wreg[d] = We[(size_t)col * INNERn + colbase + d];
        #pragma unroll
        for (int r = 0; r < 8; r++) {
            int i = i0 + ibase + 4 * r;
            float s = 0.f;
            #pragma unroll
            for (int d = 0; d < Dn; d++) s += wreg[d] * sOut[ibase + 4 * r][d];
            g_qe[(size_t)h * (Nn * DEn) + (size_t)i * DEn + col] = s;
        }
        if (col == 0) {
            #pragma unroll
            for (int r = 0; r < 8; r++) {
                int i = i0 + ibase + 4 * r;
                float sb = 0.f;
                for (int d = 0; d < Dn; d++) sb += sOut[ibase + 4 * r][d] * be[colbase + d];
                g_qbe[h * Nn + i] = sb;
            }
        }
    }
}

// ---------------- kernel 2: weights precompute: M, bvec, VW ----------------
// grid 193: [0,64) = M, 64 = bvec, [65,193) = VW (8 heads x 16 j-tiles of 32)
__global__ void __launch_bounds__(256)
wcomb_kernel(const float* __restrict__ We, const float* __restrict__ be,
             const float* __restrict__ Wo, const float* __restrict__ bo,
             const float* __restrict__ vmat)
{
    __shared__ float sV[32][68];
    __shared__ float sWo[64][132];

    const int b = blockIdx.x;
    const int t = threadIdx.x;
    if (b < 64) {
        const int h  = b >> 3;
        const int c0 = (b & 7) * 8 + (t >> 7) * 4;
        const int o  = t & 127;
        float acc[4] = {0.f, 0.f, 0.f, 0.f};
        for (int d = 0; d < 64; d++) {
            float wo = Wo[(size_t)(h * 64 + d) * DNn + o];
            #pragma unroll
            for (int cc = 0; cc < 4; cc++)
                acc[cc] += We[(size_t)(c0 + cc) * INNERn + h * 64 + d] * wo;
        }
        #pragma unroll
        for (int cc = 0; cc < 4; cc++)
            g_M[(size_t)(h * 64 + c0 + cc) * DNn + o] = acc[cc];
    } else if (b == 64) {
        if (t < 128) {
            float acc = bo[t];
            for (int k = 0; k < INNERn; k++) acc += be[k] * Wo[(size_t)k * DNn + t];
            g_bvec[t] = acc;
        }
    } else {
        const int vb = b - 65;
        const int h  = vb >> 4;
        const int j0 = (vb & 15) * 32;
        #pragma unroll
        for (int u = 0; u < 2; u++) {
            int idx = t + 256 * u;
            int j = idx >> 4, d4 = (idx & 15) * 4;
            *(float4*)&sV[j][d4] = *(const float4*)(vmat + (size_t)h * (Nn * Dn) + (size_t)(j0 + j) * Dn + d4);
        }
        #pragma unroll
        for (int u = 0; u < 8; u++) {
            int idx = t + 256 * u;
            int d = idx >> 5, o4 = (idx & 31) * 4;
            *(float4*)&sWo[d][o4] = *(const float4*)(Wo + (size_t)(h * 64 + d) * DNn + o4);
        }
        __syncthreads();

        const int jj0 = (t >> 5) * 4;
        const int oo0 = (t & 31) * 4;
        float acc[4][4];
        #pragma unroll
        for (int u = 0; u < 4; u++)
            #pragma unroll
            for (int v = 0; v < 4; v++) acc[u][v] = 0.f;

        #pragma unroll 4
        for (int d = 0; d < 64; d++) {
            float a0 = sV[jj0 + 0][d], a1 = sV[jj0 + 1][d], a2 = sV[jj0 + 2][d], a3 = sV[jj0 + 3][d];
            float4 w = *(const float4*)&sWo[d][oo0];
            acc[0][0] += a0 * w.x; acc[0][1] += a0 * w.y; acc[0][2] += a0 * w.z; acc[0][3] += a0 * w.w;
            acc[1][0] += a1 * w.x; acc[1][1] += a1 * w.y; acc[1][2] += a1 * w.z; acc[1][3] += a1 * w.w;
            acc[2][0] += a2 * w.x; acc[2][1] += a2 * w.y; acc[2][2] += a2 * w.z; acc[2][3] += a2 * w.w;
            acc[3][0] += a3 * w.x; acc[3][1] += a3 * w.y; acc[3][2] += a3 * w.z; acc[3][3] += a3 * w.w;
        }
        #pragma unroll
        for (int u = 0; u < 4; u++) {
            float4 o4 = make_float4(acc[u][0], acc[u][1], acc[u][2], acc[u][3]);
            *(float4*)(g_VW + (size_t)(h * Nn + j0 + jj0 + u) * DNn + oo0) = o4;
        }
    }
}

// ---------------- kernel 3: sim = q @ k^T + qbe ----------------
__global__ void __launch_bounds__(256)
qksim_kernel(const float* __restrict__ kmat)
{
    __shared__ float sQT[64][36];
    __shared__ float sKT[64][132];

    const int i0 = blockIdx.x * 32;
    const int j0 = blockIdx.y * 128;
    const int h  = blockIdx.z;
    const int t  = threadIdx.x;

    #pragma unroll
    for (int r = 0; r < 2; r++) {
        int idx = t + 256 * r;
        int i = idx >> 4, d4 = (idx & 15) * 4;
        float4 v = *(const float4*)(g_q + (size_t)h * (Nn * Dn) + (size_t)(i0 + i) * Dn + d4);
        sQT[d4 + 0][i] = v.x; sQT[d4 + 1][i] = v.y; sQT[d4 + 2][i] = v.z; sQT[d4 + 3][i] = v.w;
    }
    #pragma unroll
    for (int r = 0; r < 8; r++) {
        int idx = t + 256 * r;
        int j = idx >> 4, d4 = (idx & 15) * 4;
        float4 v = *(const float4*)(kmat + (size_t)h * (Nn * Dn) + (size_t)(j0 + j) * Dn + d4);
        sKT[d4 + 0][j] = v.x; sKT[d4 + 1][j] = v.y; sKT[d4 + 2][j] = v.z; sKT[d4 + 3][j] = v.w;
    }
    __syncthreads();

    const int ii0 = (t >> 5) * 4;
    const int jj0 = (t & 31) * 4;
    float acc[4][4];
    #pragma unroll
    for (int u = 0; u < 4; u++)
        #pragma unroll
        for (int v = 0; v < 4; v++) acc[u][v] = 0.f;

    #pragma unroll 4
    for (int d = 0; d < 64; d++) {
        float4 rq = *(const float4*)&sQT[d][ii0];
        float4 rk = *(const float4*)&sKT[d][jj0];
        acc[0][0] += rq.x * rk.x; acc[0][1] += rq.x * rk.y; acc[0][2] += rq.x * rk.z; acc[0][3] += rq.x * rk.w;
        acc[1][0] += rq.y * rk.x; acc[1][1] += rq.y * rk.y; acc[1][2] += rq.y * rk.z; acc[1][3] += rq.y * rk.w;
        acc[2][0] += rq.z * rk.x; acc[2][1] += rq.z * rk.y; acc[2][2] += rq.z * rk.z; acc[2][3] += rq.z * rk.w;
        acc[3][0] += rq.w * rk.x; acc[3][1] += rq.w * rk.y; acc[3][2] += rq.w * rk.z; acc[3][3] += rq.w * rk.w;
    }

    #pragma unroll
    for (int u = 0; u < 4; u++) {
        float qbe = g_qbe[h * Nn + i0 + ii0 + u];
        float4 o = make_float4(acc[u][0] + qbe, acc[u][1] + qbe, acc[u][2] + qbe, acc[u][3] + qbe);
        *(float4*)(g_sim + ((size_t)(h * Nn + i0 + ii0 + u)) * Nn + j0 + jj0) = o;
    }
}

// ---------------- kernel 4: edge_mega — edgesim + softmax + ew fused --------
#define EMS_SIM  0
#define EMS_QEP  4096
#define EMS_SINV 4608
#define EMS_RED  4624
#define EMS_E    8720
#define EM_SMEM  ((EMS_E + 128 * 68) * 4)

__global__ void __launch_bounds__(256, 3)
edge_mega_kernel(const float* __restrict__ edges)
{
    extern __shared__ float sm[];
    float* sSim  = sm + EMS_SIM;
    ull*   sQEP  = (ull*)(sm + EMS_QEP);
    float* sSinv = sm + EMS_SINV;
    ull*   sRed  = (ull*)(sm + EMS_RED);
    float* sE    = sm + EMS_E;

    const int i = blockIdx.x;
    const int t = threadIdx.x;
    const int w = t >> 5, l = t & 31;

    #pragma unroll
    for (int r = 0; r < 4; r++) {
        int idx = t + 256 * r;
        int h = idx >> 7, j4 = (idx & 127) * 4;
        *(float4*)&sSim[h * 512 + j4] = *(const float4*)(g_sim + ((size_t)(h * Nn + i)) * Nn + j4);
    }
    {
        int c = t >> 2, hp = t & 3;
        float a = g_qe[(size_t)(2 * hp)     * (Nn * DEn) + (size_t)i * DEn + c];
        float b = g_qe[(size_t)(2 * hp + 1) * (Nn * DEn) + (size_t)i * DEn + c];
        sQEP[c * 4 + hp] = pk2(a, b);
    }

    const int jl = t & 63, qq = t >> 6;
    for (int tile = 0; tile < 4; tile++) {
        const int j0 = tile * 128;
        #pragma unroll
        for (int u = 0; u < 8; u++) {
            int idx = t + 256 * u;
            int row = idx >> 4, q4 = (idx & 15) * 4;
            *(float4*)&sE[row * 68 + q4] = *(const float4*)(edges + ((size_t)i * Nn + j0 + row) * DEn + q4);
        }
        __syncthreads();

        ull a0[4] = {0, 0, 0, 0}, a1[4] = {0, 0, 0, 0};
        const int c0 = qq * 16;
        #pragma unroll
        for (int cc = 0; cc < 4; cc++) {
            const int cb = c0 + cc * 4;
            ull qr[4][4];
            #pragma unroll
            for (int k = 0; k < 4; k++)
                #pragma unroll
                for (int hp = 0; hp < 4; hp++)
                    qr[k][hp] = sQEP[(cb + k) * 4 + hp];
            float4 e0 = *(const float4*)&sE[jl * 68 + cb];
            float4 e1 = *(const float4*)&sE[(jl + 64) * 68 + cb];
            ull ed0[4] = {pk2(e0.x, e0.x), pk2(e0.y, e0.y), pk2(e0.z, e0.z), pk2(e0.w, e0.w)};
            ull ed1[4] = {pk2(e1.x, e1.x), pk2(e1.y, e1.y), pk2(e1.z, e1.z), pk2(e1.w, e1.w)};
            #pragma unroll
            for (int k = 0; k < 4; k++)
                #pragma unroll
                for (int hp = 0; hp < 4; hp++) {
                    fma2(a0[hp], ed0[k], qr[k][hp]);
                    fma2(a1[hp], ed1[k], qr[k][hp]);
                }
        }
        #pragma unroll
        for (int hp = 0; hp < 4; hp++) {
            sRed[(hp * 4 + qq) * 128 + jl]      = a0[hp];
            sRed[(hp * 4 + qq) * 128 + jl + 64] = a1[hp];
        }
        __syncthreads();

        #pragma unroll
        for (int u = 0; u < 2; u++) {
            int it = t + 256 * u;
            int hp = it >> 7, row = it & 127;
            float ax = 0.f, ay = 0.f;
            #pragma unroll
            for (int q = 0; q < 4; q++) {
                float2 f = upk2(sRed[(hp * 4 + q) * 128 + row]);
                ax += f.x; ay += f.y;
            }
            sSim[(2 * hp) * 512 + j0 + row]     += ax;
            sSim[(2 * hp + 1) * 512 + j0 + row] += ay;
        }
        __syncthreads();
    }

    {
        float vals[16];
        float mx = -1e30f;
        #pragma unroll
        for (int jc = 0; jc < 16; jc++) {
            vals[jc] = sSim[w * 512 + jc * 32 + l];
            mx = fmaxf(mx, vals[jc]);
        }
        #pragma unroll
        for (int off = 16; off > 0; off >>= 1) mx = fmaxf(mx, __shfl_xor_sync(0xffffffffu, mx, off));
        float s = 0.f;
        #pragma unroll
        for (int jc = 0; jc < 16; jc++) {
            float e = __expf(vals[jc] - mx);
            s += e;
            sSim[w * 512 + jc * 32 + l] = e;
        }
        #pragma unroll
        for (int off = 16; off > 0; off >>= 1) s += __shfl_xor_sync(0xffffffffu, s, off);
        if (l == 0) sSinv[w] = 1.0f / s;
    }
    __syncthreads();

    #pragma unroll
    for (int r = 0; r < 4; r++) {
        int idx = t + 256 * r;
        int h = idx >> 7, j4 = (idx & 127) * 4;
        *(float4*)(g_sim + ((size_t)(h * Nn + i)) * Nn + j4) = *(const float4*)&sSim[h * 512 + j4];
    }
    if (t < 8) g_sinv[t * Nn + i] = sSinv[t];

    const int cq = t & 15, jg = t >> 4;
    const int c0p = cq * 4;
    ull b[4][4];
    #pragma unroll
    for (int k = 0; k < 4; k++)
        #pragma unroll
        for (int hp = 0; hp < 4; hp++) b[k][hp] = 0ull;

    for (int tile = 0; tile < 4; tile++) {
        const int j0 = tile * 128;
        #pragma unroll
        for (int u = 0; u < 8; u++) {
            int idx = t + 256 * u;
            int row = idx >> 4, q4 = (idx & 15) * 4;
            *(float4*)&sE[row * 68 + q4] = *(const float4*)(edges + ((size_t)i * Nn + j0 + row) * DEn + q4);
        }
        __syncthreads();

        #pragma unroll
        for (int jj = 0; jj < 8; jj++) {
            const int j = jg * 8 + jj;
            const int jglob = j0 + j;
            ull pp[4];
            #pragma unroll
            for (int hp = 0; hp < 4; hp++)
                pp[hp] = pk2(sSim[(2 * hp) * 512 + jglob], sSim[(2 * hp + 1) * 512 + jglob]);
            float4 e4 = *(const float4*)&sE[j * 68 + c0p];
            ull ed[4] = {pk2(e4.x, e4.x), pk2(e4.y, e4.y), pk2(e4.z, e4.z), pk2(e4.w, e4.w)};
            #pragma unroll
            for (int k = 0; k < 4; k++)
                #pragma unroll
                for (int hp = 0; hp < 4; hp++)
                    fma2(b[k][hp], pp[hp], ed[k]);
        }
        __syncthreads();
    }

    #pragma unroll
    for (int k = 0; k < 4; k++)
        #pragma unroll
        for (int hp = 0; hp < 4; hp++) {
            ull o = __shfl_down_sync(0xffffffffu, b[k][hp], 16);
            add2(b[k][hp], o);
        }
    if (l < 16) {
        const int jg2 = w;
        #pragma unroll
        for (int k = 0; k < 4; k++)
            #pragma unroll
            for (int hp = 0; hp < 4; hp++)
                sRed[(k * 4 + hp) * 128 + jg2 * 16 + cq] = b[k][hp];
    }
    __syncthreads();

    {
        const int hp = t >> 6, c = t & 63;
        const int k = c & 3, cq2 = c >> 2;
        float ax = 0.f, ay = 0.f;
        #pragma unroll
        for (int jg2 = 0; jg2 < 8; jg2++) {
            float2 f = upk2(sRed[(k * 4 + hp) * 128 + jg2 * 16 + cq2]);
            ax += f.x; ay += f.y;
        }
        g_ew[(size_t)(2 * hp)     * (Nn * DEn) + (size_t)i * DEn + c] = ax * sSinv[2 * hp];
        g_ew[(size_t)(2 * hp + 1) * (Nn * DEn) + (size_t)i * DEn + c] = ay * sSinv[2 * hp + 1];
    }
}

// ---------------- kernel 5: out = [Pn | EW] @ [VW; M] + bvec ----------------
// grid (32 i-tiles of 16, 4 o-tiles of 32), 512 threads, k-split by 2.
#define NKC 36     // 36 chunks of 128: 32 p-chunks (K=4096) + 4 ew-chunks (K=512)

__global__ void __launch_bounds__(512)
mega_out_kernel(float* __restrict__ out)
{
    __shared__ float sA[16][132];
    __shared__ float sB[128][36];
    __shared__ float sSinv[8][16];
    __shared__ ull   sRed[512];

    const int t  = threadIdx.x;
    const int i0 = blockIdx.x * 16;
    const int c0 = blockIdx.y * 32;

    if (t < 128) {
        int h = t >> 4, r = t & 15;
        sSinv[h][r] = g_sinv[h * Nn + i0 + r];
    }
    __syncthreads();

    const int half = t >> 8;
    const int pid  = t & 255;
    const int r    = pid >> 4;
    const int cc   = (pid & 15) * 2;
    ull acc = 0;

    for (int kc = 0; kc < NKC; kc++) {
        const int kb = kc * 128;
        // A tile: 16 x 128 (normalized p, or ew)
        {
            int row = t >> 5, kk4 = (t & 31) * 4;
            float4 v;
            if (kb < 4096) {
                int h = kb >> 9;
                int j = (kb & 511) + kk4;
                v = *(const float4*)(g_sim + ((size_t)(h * Nn + i0 + row)) * Nn + j);
                float s = sSinv[h][row];
                v.x *= s; v.y *= s; v.z *= s; v.w *= s;
            } else {
                int k2 = kb - 4096 + kk4;
                int h = k2 >> 6, c = k2 & 63;
                v = *(const float4*)(g_ew + (size_t)h * (Nn * DEn) + (size_t)(i0 + row) * DEn + c);
            }
            *(float4*)&sA[row][kk4] = v;
        }
        // B tile: 128 x 32
        #pragma unroll
        for (int u = 0; u < 2; u++) {
            int idx = t + 512 * u;
            int kr = idx >> 3, q = (idx & 7) * 4;
            int k = kb + kr;
            float4 v;
            if (k < 4096) v = *(const float4*)(g_VW + (size_t)k * DNn + c0 + q);
            else          v = *(const float4*)(g_M + (size_t)(k - 4096) * DNn + c0 + q);
            *(float4*)&sB[kr][q] = v;
        }
        __syncthreads();

        const int kkb = half * 64;
        #pragma unroll 8
        for (int kk = 0; kk < 64; kk++) {
            float a = sA[r][kkb + kk];
            ull ad = pk2(a, a);
            ull wv = *(const ull*)&sB[kkb + kk][cc];
            fma2(acc, ad, wv);
        }
        __syncthreads();
    }

    sRed[t] = acc;
    __syncthreads();
    if (half == 0) {
        float2 f1 = upk2(sRed[t]);
        float2 f2 = upk2(sRed[t + 256]);
        float2 f;
        f.x = f1.x + f2.x + g_bvec[c0 + cc];
        f.y = f1.y + f2.y + g_bvec[c0 + cc + 1];
        *(float2*)(out + (size_t)(i0 + r) * DNn + c0 + cc) = f;
    }
}

// ---------------- launch ----------------
extern "C" void kernel_launch(void* const* d_in, const int* in_sizes, int n_in,
                              void* d_out, int out_size)
{
    const float* nodes = (const float*)d_in[0];
    const float* edges = (const float*)d_in[1];
    const float* Wq = (const float*)d_in[3];
    const float* bq = (const float*)d_in[4];
    const float* Wk = (const float*)d_in[5];
    const float* bk = (const float*)d_in[6];
    const float* Wv = (const float*)d_in[7];
    const float* bv = (const float*)d_in[8];
    const float* We = (const float*)d_in[9];
    const float* be = (const float*)d_in[10];
    const float* Wo = (const float*)d_in[11];
    const float* bo = (const float*)d_in[12];
    float* out = (float*)d_out;

    float* kptr; float* vptr;
    cudaGetSymbolAddress((void**)&kptr, g_k);
    cudaGetSymbolAddress((void**)&vptr, g_v);

    cudaFuncSetAttribute(edge_mega_kernel, cudaFuncAttributeMaxDynamicSharedMemorySize, EM_SMEM);

    dim3 g1(16, 24);
    qkv_kernel<<<g1, 256>>>(nodes, Wq, bq, Wk, bk, Wv, bv, We, be);
    wcomb_kernel<<<193, 256>>>(We, be, Wo, bo, vptr);
    qksim_kernel<<<dim3(16, 4, 8), 256>>>(kptr);
    edge_mega_kernel<<<Nn, 256, EM_SMEM>>>(edges);
    mega_out_kernel<<<dim3(32, 4), 512>>>(out);
}

// round 8
// speedup vs baseline: 1.0863x; 1.0863x over previous
#include <cuda_runtime.h>
#include <math.h>

#define Hn     8
#define Nn     512
#define Dn     64
#define DNn    128
#define DEn    64
#define INNERn 512

typedef unsigned long long ull;

__device__ __forceinline__ ull pk2(float lo, float hi) {
    ull r; asm("mov.b64 %0,{%1,%2};" : "=l"(r) : "f"(lo), "f"(hi)); return r;
}
__device__ __forceinline__ float2 upk2(ull v) {
    float2 r; asm("mov.b64 {%0,%1},%2;" : "=f"(r.x), "=f"(r.y) : "l"(v)); return r;
}
__device__ __forceinline__ void fma2(ull& d, ull a, ull b) {
    asm("fma.rn.f32x2 %0,%1,%2,%3;" : "=l"(d) : "l"(a), "l"(b), "l"(d));
}
__device__ __forceinline__ void add2(ull& d, ull a) {
    asm("add.rn.f32x2 %0,%1,%2;" : "=l"(d) : "l"(d), "l"(a));
}

// ---------------- scratch ----------------
__device__ float g_q  [Hn * Nn * Dn];
__device__ float g_k  [Hn * Nn * Dn];
__device__ float g_v  [Hn * Nn * Dn];
__device__ float g_qe [Hn * Nn * DEn];
__device__ float g_qbe[Hn * Nn];
__device__ float g_sim[Hn * Nn * Nn];    // qk logits, then unnormalized p
__device__ float g_sinv[Hn * Nn];
__device__ float g_ew [Hn * Nn * DEn];   // normalized
__device__ float g_M  [INNERn * DNn];
__device__ float g_VW [Hn * Nn * DNn];   // (V_h @ Wo_h)
__device__ float g_bvec[DNn];
__device__ float g_part[32 * Nn * DNn];  // 8MB epilogue partials

// ---------------- kernel 1: QKV projection (+ fused qe, qbe) --------
__global__ void __launch_bounds__(256)
qkv_kernel(const float* __restrict__ nodes,
           const float* __restrict__ Wq, const float* __restrict__ bq,
           const float* __restrict__ Wk, const float* __restrict__ bk,
           const float* __restrict__ Wv, const float* __restrict__ bv,
           const float* __restrict__ We, const float* __restrict__ be)
{
    __shared__ float sN[32][DNn];
    __shared__ float sW[DNn][64];

    const int it = blockIdx.x;
    const int ct = blockIdx.y;
    const int mat = ct >> 3;
    const int h   = ct & 7;
    const int colbase = h * 64;
    const float* W    = (mat == 0) ? Wq : (mat == 1 ? Wk : Wv);
    const float* bias = (mat == 0) ? bq : (mat == 1 ? bk : bv);
    float* out        = (mat == 0) ? g_q : (mat == 1 ? g_k : g_v);

    const int i0 = it * 32;
    const int t  = threadIdx.x;

    {
        const float4* nf = (const float4*)(nodes + (size_t)i0 * DNn);
        float4* sNf = (float4*)&sN[0][0];
        #pragma unroll
        for (int r = 0; r < 4; r++) sNf[t + 256 * r] = nf[t + 256 * r];
    }
    #pragma unroll
    for (int r = 0; r < 8; r++) {
        int idx = t + 256 * r;
        int f = idx >> 4, c4 = idx & 15;
        ((float4*)&sW[f][0])[c4] = *(const float4*)(W + (size_t)f * INNERn + colbase + c4 * 4);
    }
    __syncthreads();

    const int col   = t & 63;
    const int ibase = t >> 6;
    float acc[8];
    #pragma unroll
    for (int r = 0; r < 8; r++) acc[r] = 0.f;

    for (int f = 0; f < DNn; f++) {
        float w = sW[f][col];
        #pragma unroll
        for (int r = 0; r < 8; r++) acc[r] += sN[ibase + 4 * r][f] * w;
    }

    const float b  = bias[colbase + col];
    const float sc = (mat == 0) ? 0.125f : 1.0f;
    float vals[8];
    #pragma unroll
    for (int r = 0; r < 8; r++) {
        vals[r] = (acc[r] + b) * sc;
        int i = i0 + ibase + 4 * r;
        out[(size_t)h * (Nn * Dn) + (size_t)i * Dn + col] = vals[r];
    }

    if (mat == 0) {
        float (*sOut)[Dn] = (float(*)[Dn])&sW[0][0];
        __syncthreads();
        #pragma unroll
        for (int r = 0; r < 8; r++) sOut[ibase + 4 * r][col] = vals[r];
        __syncthreads();

        float wreg[Dn];
        #pragma unroll
        for (int d = 0; d < Dn; d++) wreg[d] = We[(size_t)col * INNERn + colbase + d];
        #pragma unroll
        for (int r = 0; r < 8; r++) {
            int i = i0 + ibase + 4 * r;
            float s = 0.f;
            #pragma unroll
            for (int d = 0; d < Dn; d++) s += wreg[d] * sOut[ibase + 4 * r][d];
            g_qe[(size_t)h * (Nn * DEn) + (size_t)i * DEn + col] = s;
        }
        if (col == 0) {
            #pragma unroll
            for (int r = 0; r < 8; r++) {
                int i = i0 + ibase + 4 * r;
                float sb = 0.f;
                for (int d = 0; d < Dn; d++) sb += sOut[ibase + 4 * r][d] * be[colbase + d];
                g_qbe[h * Nn + i] = sb;
            }
        }
    }
}

// ---------------- kernel 2: weights precompute: M, bvec, VW ----------------
__global__ void __launch_bounds__(256)
wcomb_kernel(const float* __restrict__ We, const float* __restrict__ be,
             const float* __restrict__ Wo, const float* __restrict__ bo,
             const float* __restrict__ vmat)
{
    __shared__ float sV[32][68];
    __shared__ float sWo[64][132];

    const int b = blockIdx.x;
    const int t = threadIdx.x;
    if (b < 64) {
        const int h  = b >> 3;
        const int c0 = (b & 7) * 8 + (t >> 7) * 4;
        const int o  = t & 127;
        float acc[4] = {0.f, 0.f, 0.f, 0.f};
        for (int d = 0; d < 64; d++) {
            float wo = Wo[(size_t)(h * 64 + d) * DNn + o];
            #pragma unroll
            for (int cc = 0; cc < 4; cc++)
                acc[cc] += We[(size_t)(c0 + cc) * INNERn + h * 64 + d] * wo;
        }
        #pragma unroll
        for (int cc = 0; cc < 4; cc++)
            g_M[(size_t)(h * 64 + c0 + cc) * DNn + o] = acc[cc];
    } else if (b == 64) {
        if (t < 128) {
            float acc = bo[t];
            for (int k = 0; k < INNERn; k++) acc += be[k] * Wo[(size_t)k * DNn + t];
            g_bvec[t] = acc;
        }
    } else {
        const int vb = b - 65;
        const int h  = vb >> 4;
        const int j0 = (vb & 15) * 32;
        #pragma unroll
        for (int u = 0; u < 2; u++) {
            int idx = t + 256 * u;
            int j = idx >> 4, d4 = (idx & 15) * 4;
            *(float4*)&sV[j][d4] = *(const float4*)(vmat + (size_t)h * (Nn * Dn) + (size_t)(j0 + j) * Dn + d4);
        }
        #pragma unroll
        for (int u = 0; u < 8; u++) {
            int idx = t + 256 * u;
            int d = idx >> 5, o4 = (idx & 31) * 4;
            *(float4*)&sWo[d][o4] = *(const float4*)(Wo + (size_t)(h * 64 + d) * DNn + o4);
        }
        __syncthreads();

        const int jj0 = (t >> 5) * 4;
        const int oo0 = (t & 31) * 4;
        float acc[4][4];
        #pragma unroll
        for (int u = 0; u < 4; u++)
            #pragma unroll
            for (int v = 0; v < 4; v++) acc[u][v] = 0.f;

        #pragma unroll 4
        for (int d = 0; d < 64; d++) {
            float a0 = sV[jj0 + 0][d], a1 = sV[jj0 + 1][d], a2 = sV[jj0 + 2][d], a3 = sV[jj0 + 3][d];
            float4 w = *(const float4*)&sWo[d][oo0];
            acc[0][0] += a0 * w.x; acc[0][1] += a0 * w.y; acc[0][2] += a0 * w.z; acc[0][3] += a0 * w.w;
            acc[1][0] += a1 * w.x; acc[1][1] += a1 * w.y; acc[1][2] += a1 * w.z; acc[1][3] += a1 * w.w;
            acc[2][0] += a2 * w.x; acc[2][1] += a2 * w.y; acc[2][2] += a2 * w.z; acc[2][3] += a2 * w.w;
            acc[3][0] += a3 * w.x; acc[3][1] += a3 * w.y; acc[3][2] += a3 * w.z; acc[3][3] += a3 * w.w;
        }
        #pragma unroll
        for (int u = 0; u < 4; u++) {
            float4 o4 = make_float4(acc[u][0], acc[u][1], acc[u][2], acc[u][3]);
            *(float4*)(g_VW + (size_t)(h * Nn + j0 + jj0 + u) * DNn + oo0) = o4;
        }
    }
}

// ---------------- kernel 3: sim = q @ k^T + qbe ----------------
__global__ void __launch_bounds__(256)
qksim_kernel(const float* __restrict__ kmat)
{
    __shared__ float sQT[64][36];
    __shared__ float sKT[64][132];

    const int i0 = blockIdx.x * 32;
    const int j0 = blockIdx.y * 128;
    const int h  = blockIdx.z;
    const int t  = threadIdx.x;

    #pragma unroll
    for (int r = 0; r < 2; r++) {
        int idx = t + 256 * r;
        int i = idx >> 4, d4 = (idx & 15) * 4;
        float4 v = *(const float4*)(g_q + (size_t)h * (Nn * Dn) + (size_t)(i0 + i) * Dn + d4);
        sQT[d4 + 0][i] = v.x; sQT[d4 + 1][i] = v.y; sQT[d4 + 2][i] = v.z; sQT[d4 + 3][i] = v.w;
    }
    #pragma unroll
    for (int r = 0; r < 8; r++) {
        int idx = t + 256 * r;
        int j = idx >> 4, d4 = (idx & 15) * 4;
        float4 v = *(const float4*)(kmat + (size_t)h * (Nn * Dn) + (size_t)(j0 + j) * Dn + d4);
        sKT[d4 + 0][j] = v.x; sKT[d4 + 1][j] = v.y; sKT[d4 + 2][j] = v.z; sKT[d4 + 3][j] = v.w;
    }
    __syncthreads();

    const int ii0 = (t >> 5) * 4;
    const int jj0 = (t & 31) * 4;
    float acc[4][4];
    #pragma unroll
    for (int u = 0; u < 4; u++)
        #pragma unroll
        for (int v = 0; v < 4; v++) acc[u][v] = 0.f;

    #pragma unroll 4
    for (int d = 0; d < 64; d++) {
        float4 rq = *(const float4*)&sQT[d][ii0];
        float4 rk = *(const float4*)&sKT[d][jj0];
        acc[0][0] += rq.x * rk.x; acc[0][1] += rq.x * rk.y; acc[0][2] += rq.x * rk.z; acc[0][3] += rq.x * rk.w;
        acc[1][0] += rq.y * rk.x; acc[1][1] += rq.y * rk.y; acc[1][2] += rq.y * rk.z; acc[1][3] += rq.y * rk.w;
        acc[2][0] += rq.z * rk.x; acc[2][1] += rq.z * rk.y; acc[2][2] += rq.z * rk.z; acc[2][3] += rq.z * rk.w;
        acc[3][0] += rq.w * rk.x; acc[3][1] += rq.w * rk.y; acc[3][2] += rq.w * rk.z; acc[3][3] += rq.w * rk.w;
    }

    #pragma unroll
    for (int u = 0; u < 4; u++) {
        float qbe = g_qbe[h * Nn + i0 + ii0 + u];
        float4 o = make_float4(acc[u][0] + qbe, acc[u][1] + qbe, acc[u][2] + qbe, acc[u][3] + qbe);
        *(float4*)(g_sim + ((size_t)(h * Nn + i0 + ii0 + u)) * Nn + j0 + jj0) = o;
    }
}

// ---------------- kernel 4: edge_mega — edgesim + softmax + ew fused --------
#define EMS_SIM  0
#define EMS_QEP  4096
#define EMS_SINV 4608
#define EMS_RED  4624
#define EMS_E    8720
#define EM_SMEM  ((EMS_E + 128 * 68) * 4)

__global__ void __launch_bounds__(256, 3)
edge_mega_kernel(const float* __restrict__ edges)
{
    extern __shared__ float sm[];
    float* sSim  = sm + EMS_SIM;
    ull*   sQEP  = (ull*)(sm + EMS_QEP);
    float* sSinv = sm + EMS_SINV;
    ull*   sRed  = (ull*)(sm + EMS_RED);
    float* sE    = sm + EMS_E;

    const int i = blockIdx.x;
    const int t = threadIdx.x;
    const int w = t >> 5, l = t & 31;

    #pragma unroll
    for (int r = 0; r < 4; r++) {
        int idx = t + 256 * r;
        int h = idx >> 7, j4 = (idx & 127) * 4;
        *(float4*)&sSim[h * 512 + j4] = *(const float4*)(g_sim + ((size_t)(h * Nn + i)) * Nn + j4);
    }
    {
        int c = t >> 2, hp = t & 3;
        float a = g_qe[(size_t)(2 * hp)     * (Nn * DEn) + (size_t)i * DEn + c];
        float b = g_qe[(size_t)(2 * hp + 1) * (Nn * DEn) + (size_t)i * DEn + c];
        sQEP[c * 4 + hp] = pk2(a, b);
    }

    const int jl = t & 63, qq = t >> 6;
    for (int tile = 0; tile < 4; tile++) {
        const int j0 = tile * 128;
        #pragma unroll
        for (int u = 0; u < 8; u++) {
            int idx = t + 256 * u;
            int row = idx >> 4, q4 = (idx & 15) * 4;
            *(float4*)&sE[row * 68 + q4] = *(const float4*)(edges + ((size_t)i * Nn + j0 + row) * DEn + q4);
        }
        __syncthreads();

        ull a0[4] = {0, 0, 0, 0}, a1[4] = {0, 0, 0, 0};
        const int c0 = qq * 16;
        #pragma unroll
        for (int cc = 0; cc < 4; cc++) {
            const int cb = c0 + cc * 4;
            ull qr[4][4];
            #pragma unroll
            for (int k = 0; k < 4; k++)
                #pragma unroll
                for (int hp = 0; hp < 4; hp++)
                    qr[k][hp] = sQEP[(cb + k) * 4 + hp];
            float4 e0 = *(const float4*)&sE[jl * 68 + cb];
            float4 e1 = *(const float4*)&sE[(jl + 64) * 68 + cb];
            ull ed0[4] = {pk2(e0.x, e0.x), pk2(e0.y, e0.y), pk2(e0.z, e0.z), pk2(e0.w, e0.w)};
            ull ed1[4] = {pk2(e1.x, e1.x), pk2(e1.y, e1.y), pk2(e1.z, e1.z), pk2(e1.w, e1.w)};
            #pragma unroll
            for (int k = 0; k < 4; k++)
                #pragma unroll
                for (int hp = 0; hp < 4; hp++) {
                    fma2(a0[hp], ed0[k], qr[k][hp]);
                    fma2(a1[hp], ed1[k], qr[k][hp]);
                }
        }
        #pragma unroll
        for (int hp = 0; hp < 4; hp++) {
            sRed[(hp * 4 + qq) * 128 + jl]      = a0[hp];
            sRed[(hp * 4 + qq) * 128 + jl + 64] = a1[hp];
        }
        __syncthreads();

        #pragma unroll
        for (int u = 0; u < 2; u++) {
            int it = t + 256 * u;
            int hp = it >> 7, row = it & 127;
            float ax = 0.f, ay = 0.f;
            #pragma unroll
            for (int q = 0; q < 4; q++) {
                float2 f = upk2(sRed[(hp * 4 + q) * 128 + row]);
                ax += f.x; ay += f.y;
            }
            sSim[(2 * hp) * 512 + j0 + row]     += ax;
            sSim[(2 * hp + 1) * 512 + j0 + row] += ay;
        }
        __syncthreads();
    }

    {
        float vals[16];
        float mx = -1e30f;
        #pragma unroll
        for (int jc = 0; jc < 16; jc++) {
            vals[jc] = sSim[w * 512 + jc * 32 + l];
            mx = fmaxf(mx, vals[jc]);
        }
        #pragma unroll
        for (int off = 16; off > 0; off >>= 1) mx = fmaxf(mx, __shfl_xor_sync(0xffffffffu, mx, off));
        float s = 0.f;
        #pragma unroll
        for (int jc = 0; jc < 16; jc++) {
            float e = __expf(vals[jc] - mx);
            s += e;
            sSim[w * 512 + jc * 32 + l] = e;
        }
        #pragma unroll
        for (int off = 16; off > 0; off >>= 1) s += __shfl_xor_sync(0xffffffffu, s, off);
        if (l == 0) sSinv[w] = 1.0f / s;
    }
    __syncthreads();

    #pragma unroll
    for (int r = 0; r < 4; r++) {
        int idx = t + 256 * r;
        int h = idx >> 7, j4 = (idx & 127) * 4;
        *(float4*)(g_sim + ((size_t)(h * Nn + i)) * Nn + j4) = *(const float4*)&sSim[h * 512 + j4];
    }
    if (t < 8) g_sinv[t * Nn + i] = sSinv[t];

    const int cq = t & 15, jg = t >> 4;
    const int c0p = cq * 4;
    ull b[4][4];
    #pragma unroll
    for (int k = 0; k < 4; k++)
        #pragma unroll
        for (int hp = 0; hp < 4; hp++) b[k][hp] = 0ull;

    for (int tile = 0; tile < 4; tile++) {
        const int j0 = tile * 128;
        #pragma unroll
        for (int u = 0; u < 8; u++) {
            int idx = t + 256 * u;
            int row = idx >> 4, q4 = (idx & 15) * 4;
            *(float4*)&sE[row * 68 + q4] = *(const float4*)(edges + ((size_t)i * Nn + j0 + row) * DEn + q4);
        }
        __syncthreads();

        #pragma unroll
        for (int jj = 0; jj < 8; jj++) {
            const int j = jg * 8 + jj;
            const int jglob = j0 + j;
            ull pp[4];
            #pragma unroll
            for (int hp = 0; hp < 4; hp++)
                pp[hp] = pk2(sSim[(2 * hp) * 512 + jglob], sSim[(2 * hp + 1) * 512 + jglob]);
            float4 e4 = *(const float4*)&sE[j * 68 + c0p];
            ull ed[4] = {pk2(e4.x, e4.x), pk2(e4.y, e4.y), pk2(e4.z, e4.z), pk2(e4.w, e4.w)};
            #pragma unroll
            for (int k = 0; k < 4; k++)
                #pragma unroll
                for (int hp = 0; hp < 4; hp++)
                    fma2(b[k][hp], pp[hp], ed[k]);
        }
        __syncthreads();
    }

    #pragma unroll
    for (int k = 0; k < 4; k++)
        #pragma unroll
        for (int hp = 0; hp < 4; hp++) {
            ull o = __shfl_down_sync(0xffffffffu, b[k][hp], 16);
            add2(b[k][hp], o);
        }
    if (l < 16) {
        const int jg2 = w;
        #pragma unroll
        for (int k = 0; k < 4; k++)
            #pragma unroll
            for (int hp = 0; hp < 4; hp++)
                sRed[(k * 4 + hp) * 128 + jg2 * 16 + cq] = b[k][hp];
    }
    __syncthreads();

    {
        const int hp = t >> 6, c = t & 63;
        const int k = c & 3, cq2 = c >> 2;
        float ax = 0.f, ay = 0.f;
        #pragma unroll
        for (int jg2 = 0; jg2 < 8; jg2++) {
            float2 f = upk2(sRed[(k * 4 + hp) * 128 + jg2 * 16 + cq2]);
            ax += f.x; ay += f.y;
        }
        g_ew[(size_t)(2 * hp)     * (Nn * DEn) + (size_t)i * DEn + c] = ax * sSinv[2 * hp];
        g_ew[(size_t)(2 * hp + 1) * (Nn * DEn) + (size_t)i * DEn + c] = ay * sSinv[2 * hp + 1];
    }
}

// ---------------- kernel 5: epilogue GEMM partials ----------------
// grid (4 i-tiles, 32 = h*4+ks), 256 threads. Block tile 128i x 128o, K=128 (+64 EW when ks==3).
// Thread tile 8x8. A reads broadcast LDS.32, B reads broadcast LDS.128 -> fma2-bound.
#define GS_A 0                       // sA[128][68]
#define GS_B (128 * 68)              // sB[64][132]
#define GS_S (GS_B + 64 * 132)       // sSinv[128]
#define GO_SMEM ((GS_S + 128) * 4)

__global__ void __launch_bounds__(256)
gemm_out_kernel()
{
    extern __shared__ float gsm[];
    float* sA    = gsm + GS_A;       // [i][k] rows of 68
    float* sB    = gsm + GS_B;       // [k][o] rows of 132
    float* sSinv = gsm + GS_S;

    const int t  = threadIdx.x;
    const int i0 = blockIdx.x * 128;
    const int h  = blockIdx.y >> 2;
    const int ks = blockIdx.y & 3;

    if (t < 128) sSinv[t] = g_sinv[h * Nn + i0 + t];
    __syncthreads();

    const int ib = (t & 15) * 8;
    const int ob = (t >> 4) * 8;

    ull acc[8][4];
    #pragma unroll
    for (int ii = 0; ii < 8; ii++)
        #pragma unroll
        for (int uu = 0; uu < 4; uu++) acc[ii][uu] = 0ull;

    const int nsub = (ks == 3) ? 3 : 2;
    for (int sub = 0; sub < nsub; sub++) {
        if (sub < 2) {
            const int kb = ks * 128 + sub * 64;
            #pragma unroll
            for (int u = 0; u < 8; u++) {
                int idx = t + 256 * u;
                int k4 = (idx & 15) * 4;
                int i  = idx >> 4;
                float4 v = *(const float4*)(g_sim + ((size_t)(h * Nn + i0 + i)) * Nn + kb + k4);
                float s = sSinv[i];
                v.x *= s; v.y *= s; v.z *= s; v.w *= s;
                float* d = sA + i * 68 + k4;
                d[0] = v.x; d[1] = v.y; d[2] = v.z; d[3] = v.w;
            }
            #pragma unroll
            for (int u = 0; u < 8; u++) {
                int idx = t + 256 * u;
                int o4 = (idx & 31) * 4;
                int k  = idx >> 5;
                *(float4*)&sB[k * 132 + o4] = *(const float4*)(g_VW + ((size_t)(h * Nn + kb + k)) * DNn + o4);
            }
        } else {
            #pragma unroll
            for (int u = 0; u < 8; u++) {
                int idx = t + 256 * u;
                int k4 = (idx & 15) * 4;
                int i  = idx >> 4;
                float4 v = *(const float4*)(g_ew + (size_t)h * (Nn * DEn) + (size_t)(i0 + i) * DEn + k4);
                float* d = sA + i * 68 + k4;
                d[0] = v.x; d[1] = v.y; d[2] = v.z; d[3] = v.w;
            }
            #pragma unroll
            for (int u = 0; u < 8; u++) {
                int idx = t + 256 * u;
                int o4 = (idx & 31) * 4;
                int k  = idx >> 5;
                *(float4*)&sB[k * 132 + o4] = *(const float4*)(g_M + ((size_t)(h * 64 + k)) * DNn + o4);
            }
        }
        __syncthreads();

        #pragma unroll 4
        for (int k = 0; k < 64; k++) {
            ulonglong2 b01 = *(const ulonglong2*)&sB[k * 132 + ob];
            ulonglong2 b23 = *(const ulonglong2*)&sB[k * 132 + ob + 4];
            #pragma unroll
            for (int ii = 0; ii < 8; ii++) {
                float a = sA[(ib + ii) * 68 + k];
                ull ad = pk2(a, a);
                fma2(acc[ii][0], ad, b01.x);
                fma2(acc[ii][1], ad, b01.y);
                fma2(acc[ii][2], ad, b23.x);
                fma2(acc[ii][3], ad, b23.y);
            }
        }
        __syncthreads();
    }

    float* pp = g_part + (size_t)blockIdx.y * (Nn * DNn);
    #pragma unroll
    for (int ii = 0; ii < 8; ii++) {
        #pragma unroll
        for (int uu = 0; uu < 4; uu++) {
            float2 f = upk2(acc[ii][uu]);
            *(float2*)(pp + (size_t)(i0 + ib + ii) * DNn + ob + uu * 2) = f;
        }
    }
}

// ---------------- kernel 6: reduce partials + bvec -> out ----------------
__global__ void __launch_bounds__(256)
reduce_out_kernel(float* __restrict__ out)
{
    const int idx = blockIdx.x * 256 + threadIdx.x;
    float a0 = 0.f, a1 = 0.f, a2 = 0.f, a3 = 0.f;
    #pragma unroll
    for (int s = 0; s < 32; s += 4) {
        a0 += g_part[(size_t)s       * (Nn * DNn) + idx];
        a1 += g_part[(size_t)(s + 1) * (Nn * DNn) + idx];
        a2 += g_part[(size_t)(s + 2) * (Nn * DNn) + idx];
        a3 += g_part[(size_t)(s + 3) * (Nn * DNn) + idx];
    }
    out[idx] = (a0 + a1) + (a2 + a3) + g_bvec[idx & 127];
}

// ---------------- launch ----------------
extern "C" void kernel_launch(void* const* d_in, const int* in_sizes, int n_in,
                              void* d_out, int out_size)
{
    const float* nodes = (const float*)d_in[0];
    const float* edges = (const float*)d_in[1];
    const float* Wq = (const float*)d_in[3];
    const float* bq = (const float*)d_in[4];
    const float* Wk = (const float*)d_in[5];
    const float* bk = (const float*)d_in[6];
    const float* Wv = (const float*)d_in[7];
    const float* bv = (const float*)d_in[8];
    const float* We = (const float*)d_in[9];
    const float* be = (const float*)d_in[10];
    const float* Wo = (const float*)d_in[11];
    const float* bo = (const float*)d_in[12];
    float* out = (float*)d_out;

    float* kptr; float* vptr;
    cudaGetSymbolAddress((void**)&kptr, g_k);
    cudaGetSymbolAddress((void**)&vptr, g_v);

    cudaFuncSetAttribute(edge_mega_kernel, cudaFuncAttributeMaxDynamicSharedMemorySize, EM_SMEM);
    cudaFuncSetAttribute(gemm_out_kernel, cudaFuncAttributeMaxDynamicSharedMemorySize, GO_SMEM);

    dim3 g1(16, 24);
    qkv_kernel<<<g1, 256>>>(nodes, Wq, bq, Wk, bk, Wv, bv, We, be);
    wcomb_kernel<<<193, 256>>>(We, be, Wo, bo, vptr);
    qksim_kernel<<<dim3(16, 4, 8), 256>>>(kptr);
    edge_mega_kernel<<<Nn, 256, EM_SMEM>>>(edges);
    gemm_out_kernel<<<dim3(4, 32), 256, GO_SMEM>>>();
    reduce_out_kernel<<<(Nn * DNn) / 256, 256>>>(out);
}

// round 9
// speedup vs baseline: 1.4469x; 1.3320x over previous
#include <cuda_runtime.h>
#include <math.h>

#define Hn     8
#define Nn     512
#define Dn     64
#define DNn    128
#define DEn    64
#define INNERn 512

typedef unsigned long long ull;

__device__ __forceinline__ ull pk2(float lo, float hi) {
    ull r; asm("mov.b64 %0,{%1,%2};" : "=l"(r) : "f"(lo), "f"(hi)); return r;
}
__device__ __forceinline__ float2 upk2(ull v) {
    float2 r; asm("mov.b64 {%0,%1},%2;" : "=f"(r.x), "=f"(r.y) : "l"(v)); return r;
}
__device__ __forceinline__ void fma2(ull& d, ull a, ull b) {
    asm("fma.rn.f32x2 %0,%1,%2,%3;" : "=l"(d) : "l"(a), "l"(b), "l"(d));
}
__device__ __forceinline__ void add2(ull& d, ull a) {
    asm("add.rn.f32x2 %0,%1,%2;" : "=l"(d) : "l"(d), "l"(a));
}

// ---------------- scratch ----------------
__device__ float g_q  [Hn * Nn * Dn];
__device__ float g_k  [Hn * Nn * Dn];
__device__ float g_v  [Hn * Nn * Dn];
__device__ float g_qe [Hn * Nn * DEn];
__device__ float g_qbe[Hn * Nn];
__device__ float g_sim[Hn * Nn * Nn];    // qk logits, then unnormalized p
__device__ float g_sinv[Hn * Nn];
__device__ float g_ew [Hn * Nn * DEn];   // normalized
__device__ float g_M  [INNERn * DNn];
__device__ float g_VW [Hn * Nn * DNn];   // (V_h @ Wo_h)
__device__ float g_bvec[DNn];
__device__ float g_part[32 * Nn * DNn];  // 8MB epilogue partials

// ---------------- kernel 1: QKV projection (+ fused qe, qbe) --------
__global__ void __launch_bounds__(256)
qkv_kernel(const float* __restrict__ nodes,
           const float* __restrict__ Wq, const float* __restrict__ bq,
           const float* __restrict__ Wk, const float* __restrict__ bk,
           const float* __restrict__ Wv, const float* __restrict__ bv,
           const float* __restrict__ We, const float* __restrict__ be)
{
    __shared__ float sN[32][DNn];
    __shared__ float sW[DNn][64];

    const int it = blockIdx.x;
    const int ct = blockIdx.y;
    const int mat = ct >> 3;
    const int h   = ct & 7;
    const int colbase = h * 64;
    const float* W    = (mat == 0) ? Wq : (mat == 1 ? Wk : Wv);
    const float* bias = (mat == 0) ? bq : (mat == 1 ? bk : bv);
    float* out        = (mat == 0) ? g_q : (mat == 1 ? g_k : g_v);

    const int i0 = it * 32;
    const int t  = threadIdx.x;

    {
        const float4* nf = (const float4*)(nodes + (size_t)i0 * DNn);
        float4* sNf = (float4*)&sN[0][0];
        #pragma unroll
        for (int r = 0; r < 4; r++) sNf[t + 256 * r] = nf[t + 256 * r];
    }
    #pragma unroll
    for (int r = 0; r < 8; r++) {
        int idx = t + 256 * r;
        int f = idx >> 4, c4 = idx & 15;
        ((float4*)&sW[f][0])[c4] = *(const float4*)(W + (size_t)f * INNERn + colbase + c4 * 4);
    }
    __syncthreads();

    const int col   = t & 63;
    const int ibase = t >> 6;
    float acc[8];
    #pragma unroll
    for (int r = 0; r < 8; r++) acc[r] = 0.f;

    #pragma unroll 2
    for (int f4 = 0; f4 < 32; f4++) {
        float w0 = sW[f4 * 4 + 0][col];
        float w1 = sW[f4 * 4 + 1][col];
        float w2 = sW[f4 * 4 + 2][col];
        float w3 = sW[f4 * 4 + 3][col];
        #pragma unroll
        for (int r = 0; r < 8; r++) {
            float4 nv = *(const float4*)&sN[ibase + 4 * r][f4 * 4];
            acc[r] += nv.x * w0 + nv.y * w1 + nv.z * w2 + nv.w * w3;
        }
    }

    const float b  = bias[colbase + col];
    const float sc = (mat == 0) ? 0.125f : 1.0f;
    float vals[8];
    #pragma unroll
    for (int r = 0; r < 8; r++) {
        vals[r] = (acc[r] + b) * sc;
        int i = i0 + ibase + 4 * r;
        out[(size_t)h * (Nn * Dn) + (size_t)i * Dn + col] = vals[r];
    }

    if (mat == 0) {
        float (*sOut)[Dn] = (float(*)[Dn])&sW[0][0];
        __syncthreads();
        #pragma unroll
        for (int r = 0; r < 8; r++) sOut[ibase + 4 * r][col] = vals[r];
        __syncthreads();

        float wreg[Dn];
        #pragma unroll
        for (int d = 0; d < Dn; d++) wreg[d] = We[(size_t)col * INNERn + colbase + d];
        #pragma unroll
        for (int r = 0; r < 8; r++) {
            int i = i0 + ibase + 4 * r;
            float s = 0.f;
            #pragma unroll
            for (int d = 0; d < Dn; d++) s += wreg[d] * sOut[ibase + 4 * r][d];
            g_qe[(size_t)h * (Nn * DEn) + (size_t)i * DEn + col] = s;
        }
        if (col == 0) {
            #pragma unroll
            for (int r = 0; r < 8; r++) {
                int i = i0 + ibase + 4 * r;
                float sb = 0.f;
                for (int d = 0; d < Dn; d++) sb += sOut[ibase + 4 * r][d] * be[colbase + d];
                g_qbe[h * Nn + i] = sb;
            }
        }
    }
}

// ---------------- kernel 2: weights precompute: M, bvec, VW ----------------
__global__ void __launch_bounds__(256)
wcomb_kernel(const float* __restrict__ We, const float* __restrict__ be,
             const float* __restrict__ Wo, const float* __restrict__ bo,
             const float* __restrict__ vmat)
{
    __shared__ float sV[32][68];
    __shared__ float sWo[64][132];
    __shared__ float sRed[256];

    const int b = blockIdx.x;
    const int t = threadIdx.x;
    if (b < 64) {
        const int h  = b >> 3;
        const int c0 = (b & 7) * 8 + (t >> 7) * 4;
        const int o  = t & 127;
        float acc[4] = {0.f, 0.f, 0.f, 0.f};
        #pragma unroll 4
        for (int d = 0; d < 64; d++) {
            float wo = Wo[(size_t)(h * 64 + d) * DNn + o];
            #pragma unroll
            for (int cc = 0; cc < 4; cc++)
                acc[cc] += We[(size_t)(c0 + cc) * INNERn + h * 64 + d] * wo;
        }
        #pragma unroll
        for (int cc = 0; cc < 4; cc++)
            g_M[(size_t)(h * 64 + c0 + cc) * DNn + o] = acc[cc];
    } else if (b == 64) {
        const int col = t & 127;
        const int ks  = t >> 7;
        float acc = 0.f;
        #pragma unroll 8
        for (int k = ks * 256; k < ks * 256 + 256; k++)
            acc += be[k] * Wo[(size_t)k * DNn + col];
        sRed[t] = acc;
        __syncthreads();
        if (t < 128) g_bvec[t] = sRed[t] + sRed[t + 128] + bo[t];
    } else {
        const int vb = b - 65;
        const int h  = vb >> 4;
        const int j0 = (vb & 15) * 32;
        #pragma unroll
        for (int u = 0; u < 2; u++) {
            int idx = t + 256 * u;
            int j = idx >> 4, d4 = (idx & 15) * 4;
            *(float4*)&sV[j][d4] = *(const float4*)(vmat + (size_t)h * (Nn * Dn) + (size_t)(j0 + j) * Dn + d4);
        }
        #pragma unroll
        for (int u = 0; u < 8; u++) {
            int idx = t + 256 * u;
            int d = idx >> 5, o4 = (idx & 31) * 4;
            *(float4*)&sWo[d][o4] = *(const float4*)(Wo + (size_t)(h * 64 + d) * DNn + o4);
        }
        __syncthreads();

        const int jj0 = (t >> 5) * 4;
        const int oo0 = (t & 31) * 4;
        float acc[4][4];
        #pragma unroll
        for (int u = 0; u < 4; u++)
            #pragma unroll
            for (int v = 0; v < 4; v++) acc[u][v] = 0.f;

        #pragma unroll 4
        for (int d = 0; d < 64; d++) {
            float a0 = sV[jj0 + 0][d], a1 = sV[jj0 + 1][d], a2 = sV[jj0 + 2][d], a3 = sV[jj0 + 3][d];
            float4 w = *(const float4*)&sWo[d][oo0];
            acc[0][0] += a0 * w.x; acc[0][1] += a0 * w.y; acc[0][2] += a0 * w.z; acc[0][3] += a0 * w.w;
            acc[1][0] += a1 * w.x; acc[1][1] += a1 * w.y; acc[1][2] += a1 * w.z; acc[1][3] += a1 * w.w;
            acc[2][0] += a2 * w.x; acc[2][1] += a2 * w.y; acc[2][2] += a2 * w.z; acc[2][3] += a2 * w.w;
            acc[3][0] += a3 * w.x; acc[3][1] += a3 * w.y; acc[3][2] += a3 * w.z; acc[3][3] += a3 * w.w;
        }
        #pragma unroll
        for (int u = 0; u < 4; u++) {
            float4 o4 = make_float4(acc[u][0], acc[u][1], acc[u][2], acc[u][3]);
            *(float4*)(g_VW + (size_t)(h * Nn + j0 + jj0 + u) * DNn + oo0) = o4;
        }
    }
}

// ---------------- kernel 3: sim = q @ k^T + qbe ----------------
__global__ void __launch_bounds__(256)
qksim_kernel(const float* __restrict__ kmat)
{
    __shared__ float sQT[64][36];
    __shared__ float sKT[64][132];

    const int i0 = blockIdx.x * 32;
    const int j0 = blockIdx.y * 128;
    const int h  = blockIdx.z;
    const int t  = threadIdx.x;

    #pragma unroll
    for (int r = 0; r < 2; r++) {
        int idx = t + 256 * r;
        int i = idx >> 4, d4 = (idx & 15) * 4;
        float4 v = *(const float4*)(g_q + (size_t)h * (Nn * Dn) + (size_t)(i0 + i) * Dn + d4);
        sQT[d4 + 0][i] = v.x; sQT[d4 + 1][i] = v.y; sQT[d4 + 2][i] = v.z; sQT[d4 + 3][i] = v.w;
    }
    #pragma unroll
    for (int r = 0; r < 8; r++) {
        int idx = t + 256 * r;
        int j = idx >> 4, d4 = (idx & 15) * 4;
        float4 v = *(const float4*)(kmat + (size_t)h * (Nn * Dn) + (size_t)(j0 + j) * Dn + d4);
        sKT[d4 + 0][j] = v.x; sKT[d4 + 1][j] = v.y; sKT[d4 + 2][j] = v.z; sKT[d4 + 3][j] = v.w;
    }
    __syncthreads();

    const int ii0 = (t >> 5) * 4;
    const int jj0 = (t & 31) * 4;
    float acc[4][4];
    #pragma unroll
    for (int u = 0; u < 4; u++)
        #pragma unroll
        for (int v = 0; v < 4; v++) acc[u][v] = 0.f;

    #pragma unroll 4
    for (int d = 0; d < 64; d++) {
        float4 rq = *(const float4*)&sQT[d][ii0];
        float4 rk = *(const float4*)&sKT[d][jj0];
        acc[0][0] += rq.x * rk.x; acc[0][1] += rq.x * rk.y; acc[0][2] += rq.x * rk.z; acc[0][3] += rq.x * rk.w;
        acc[1][0] += rq.y * rk.x; acc[1][1] += rq.y * rk.y; acc[1][2] += rq.y * rk.z; acc[1][3] += rq.y * rk.w;
        acc[2][0] += rq.z * rk.x; acc[2][1] += rq.z * rk.y; acc[2][2] += rq.z * rk.z; acc[2][3] += rq.z * rk.w;
        acc[3][0] += rq.w * rk.x; acc[3][1] += rq.w * rk.y; acc[3][2] += rq.w * rk.z; acc[3][3] += rq.w * rk.w;
    }

    #pragma unroll
    for (int u = 0; u < 4; u++) {
        float qbe = g_qbe[h * Nn + i0 + ii0 + u];
        float4 o = make_float4(acc[u][0] + qbe, acc[u][1] + qbe, acc[u][2] + qbe, acc[u][3] + qbe);
        *(float4*)(g_sim + ((size_t)(h * Nn + i0 + ii0 + u)) * Nn + j0 + jj0) = o;
    }
}

// ---------------- kernel 4: edge_mega — edgesim + softmax + ew fused --------
#define EMS_SIM  0
#define EMS_QEP  4096
#define EMS_SINV 4608
#define EMS_RED  4624
#define EMS_E    8720
#define EM_SMEM  ((EMS_E + 128 * 68) * 4)

__global__ void __launch_bounds__(256, 3)
edge_mega_kernel(const float* __restrict__ edges)
{
    extern __shared__ float sm[];
    float* sSim  = sm + EMS_SIM;
    ull*   sQEP  = (ull*)(sm + EMS_QEP);
    float* sSinv = sm + EMS_SINV;
    ull*   sRed  = (ull*)(sm + EMS_RED);
    float* sE    = sm + EMS_E;

    const int i = blockIdx.x;
    const int t = threadIdx.x;
    const int w = t >> 5, l = t & 31;

    #pragma unroll
    for (int r = 0; r < 4; r++) {
        int idx = t + 256 * r;
        int h = idx >> 7, j4 = (idx & 127) * 4;
        *(float4*)&sSim[h * 512 + j4] = *(const float4*)(g_sim + ((size_t)(h * Nn + i)) * Nn + j4);
    }
    {
        int c = t >> 2, hp = t & 3;
        float a = g_qe[(size_t)(2 * hp)     * (Nn * DEn) + (size_t)i * DEn + c];
        float b = g_qe[(size_t)(2 * hp + 1) * (Nn * DEn) + (size_t)i * DEn + c];
        sQEP[c * 4 + hp] = pk2(a, b);
    }

    const int jl = t & 63, qq = t >> 6;
    for (int tile = 0; tile < 4; tile++) {
        const int j0 = tile * 128;
        #pragma unroll
        for (int u = 0; u < 8; u++) {
            int idx = t + 256 * u;
            int row = idx >> 4, q4 = (idx & 15) * 4;
            *(float4*)&sE[row * 68 + q4] = *(const float4*)(edges + ((size_t)i * Nn + j0 + row) * DEn + q4);
        }
        __syncthreads();

        ull a0[4] = {0, 0, 0, 0}, a1[4] = {0, 0, 0, 0};
        const int c0 = qq * 16;
        #pragma unroll
        for (int cc = 0; cc < 4; cc++) {
            const int cb = c0 + cc * 4;
            ull qr[4][4];
            #pragma unroll
            for (int k = 0; k < 4; k++)
                #pragma unroll
                for (int hp = 0; hp < 4; hp++)
                    qr[k][hp] = sQEP[(cb + k) * 4 + hp];
            float4 e0 = *(const float4*)&sE[jl * 68 + cb];
            float4 e1 = *(const float4*)&sE[(jl + 64) * 68 + cb];
            ull ed0[4] = {pk2(e0.x, e0.x), pk2(e0.y, e0.y), pk2(e0.z, e0.z), pk2(e0.w, e0.w)};
            ull ed1[4] = {pk2(e1.x, e1.x), pk2(e1.y, e1.y), pk2(e1.z, e1.z), pk2(e1.w, e1.w)};
            #pragma unroll
            for (int k = 0; k < 4; k++)
                #pragma unroll
                for (int hp = 0; hp < 4; hp++) {
                    fma2(a0[hp], ed0[k], qr[k][hp]);
                    fma2(a1[hp], ed1[k], qr[k][hp]);
                }
        }
        #pragma unroll
        for (int hp = 0; hp < 4; hp++) {
            sRed[(hp * 4 + qq) * 128 + jl]      = a0[hp];
            sRed[(hp * 4 + qq) * 128 + jl + 64] = a1[hp];
        }
        __syncthreads();

        #pragma unroll
        for (int u = 0; u < 2; u++) {
            int it = t + 256 * u;
            int hp = it >> 7, row = it & 127;
            float ax = 0.f, ay = 0.f;
            #pragma unroll
            for (int q = 0; q < 4; q++) {
                float2 f = upk2(sRed[(hp * 4 + q) * 128 + row]);
                ax += f.x; ay += f.y;
            }
            sSim[(2 * hp) * 512 + j0 + row]     += ax;
            sSim[(2 * hp + 1) * 512 + j0 + row] += ay;
        }
        __syncthreads();
    }

    {
        float vals[16];
        float mx = -1e30f;
        #pragma unroll
        for (int jc = 0; jc < 16; jc++) {
            vals[jc] = sSim[w * 512 + jc * 32 + l];
            mx = fmaxf(mx, vals[jc]);
        }
        #pragma unroll
        for (int off = 16; off > 0; off >>= 1) mx = fmaxf(mx, __shfl_xor_sync(0xffffffffu, mx, off));
        float s = 0.f;
        #pragma unroll
        for (int jc = 0; jc < 16; jc++) {
            float e = __expf(vals[jc] - mx);
            s += e;
            sSim[w * 512 + jc * 32 + l] = e;
        }
        #pragma unroll
        for (int off = 16; off > 0; off >>= 1) s += __shfl_xor_sync(0xffffffffu, s, off);
        if (l == 0) sSinv[w] = 1.0f / s;
    }
    __syncthreads();

    #pragma unroll
    for (int r = 0; r < 4; r++) {
        int idx = t + 256 * r;
        int h = idx >> 7, j4 = (idx & 127) * 4;
        *(float4*)(g_sim + ((size_t)(h * Nn + i)) * Nn + j4) = *(const float4*)&sSim[h * 512 + j4];
    }
    if (t < 8) g_sinv[t * Nn + i] = sSinv[t];

    const int cq = t & 15, jg = t >> 4;
    const int c0p = cq * 4;
    ull b[4][4];
    #pragma unroll
    for (int k = 0; k < 4; k++)
        #pragma unroll
        for (int hp = 0; hp < 4; hp++) b[k][hp] = 0ull;

    for (int tile = 0; tile < 4; tile++) {
        const int j0 = tile * 128;
        #pragma unroll
        for (int u = 0; u < 8; u++) {
            int idx = t + 256 * u;
            int row = idx >> 4, q4 = (idx & 15) * 4;
            *(float4*)&sE[row * 68 + q4] = *(const float4*)(edges + ((size_t)i * Nn + j0 + row) * DEn + q4);
        }
        __syncthreads();

        #pragma unroll
        for (int jj = 0; jj < 8; jj++) {
            const int j = jg * 8 + jj;
            const int jglob = j0 + j;
            ull pp[4];
            #pragma unroll
            for (int hp = 0; hp < 4; hp++)
                pp[hp] = pk2(sSim[(2 * hp) * 512 + jglob], sSim[(2 * hp + 1) * 512 + jglob]);
            float4 e4 = *(const float4*)&sE[j * 68 + c0p];
            ull ed[4] = {pk2(e4.x, e4.x), pk2(e4.y, e4.y), pk2(e4.z, e4.z), pk2(e4.w, e4.w)};
            #pragma unroll
            for (int k = 0; k < 4; k++)
                #pragma unroll
                for (int hp = 0; hp < 4; hp++)
                    fma2(b[k][hp], pp[hp], ed[k]);
        }
        __syncthreads();
    }

    #pragma unroll
    for (int k = 0; k < 4; k++)
        #pragma unroll
        for (int hp = 0; hp < 4; hp++) {
            ull o = __shfl_down_sync(0xffffffffu, b[k][hp], 16);
            add2(b[k][hp], o);
        }
    if (l < 16) {
        const int jg2 = w;
        #pragma unroll
        for (int k = 0; k < 4; k++)
            #pragma unroll
            for (int hp = 0; hp < 4; hp++)
                sRed[(k * 4 + hp) * 128 + jg2 * 16 + cq] = b[k][hp];
    }
    __syncthreads();

    {
        const int hp = t >> 6, c = t & 63;
        const int k = c & 3, cq2 = c >> 2;
        float ax = 0.f, ay = 0.f;
        #pragma unroll
        for (int jg2 = 0; jg2 < 8; jg2++) {
            float2 f = upk2(sRed[(k * 4 + hp) * 128 + jg2 * 16 + cq2]);
            ax += f.x; ay += f.y;
        }
        g_ew[(size_t)(2 * hp)     * (Nn * DEn) + (size_t)i * DEn + c] = ax * sSinv[2 * hp];
        g_ew[(size_t)(2 * hp + 1) * (Nn * DEn) + (size_t)i * DEn + c] = ay * sSinv[2 * hp + 1];
    }
}

// ---------------- kernel 5: epilogue GEMM partials ----------------
// grid (4 i-tiles, 32 = h*4+ks), 512 threads. Block tile 128i x 128o.
// Warp owns 8 uniform i-rows (A = broadcast LDS.32); lane owns 4 o's (B = LDS.128).
#define GS_A 0                       // sA[128][68]
#define GS_B (128 * 68)              // sB[64][132]
#define GS_S (GS_B + 64 * 132)       // sSinv[128]
#define GO_SMEM ((GS_S + 128) * 4)

__global__ void __launch_bounds__(512)
gemm_out_kernel()
{
    extern __shared__ float gsm[];
    float* sA    = gsm + GS_A;
    float* sB    = gsm + GS_B;
    float* sSinv = gsm + GS_S;

    const int t  = threadIdx.x;
    const int i0 = blockIdx.x * 128;
    const int h  = blockIdx.y >> 2;
    const int ks = blockIdx.y & 3;

    if (t < 128) sSinv[t] = g_sinv[h * Nn + i0 + t];
    __syncthreads();

    const int warp = t >> 5, lane = t & 31;
    const int ib = warp * 8;        // warp-uniform i-block
    const int ob = lane * 4;        // lane-spread o's

    ull acc[8][2];
    #pragma unroll
    for (int ii = 0; ii < 8; ii++) { acc[ii][0] = 0ull; acc[ii][1] = 0ull; }

    const int nsub = (ks == 3) ? 3 : 2;
    for (int sub = 0; sub < nsub; sub++) {
        if (sub < 2) {
            const int kb = ks * 128 + sub * 64;
            #pragma unroll
            for (int u = 0; u < 4; u++) {
                int idx = t + 512 * u;
                int k4 = (idx & 15) * 4;
                int i  = idx >> 4;
                float4 v = *(const float4*)(g_sim + ((size_t)(h * Nn + i0 + i)) * Nn + kb + k4);
                float s = sSinv[i];
                v.x *= s; v.y *= s; v.z *= s; v.w *= s;
                *(float4*)&sA[i * 68 + k4] = v;
            }
            #pragma unroll
            for (int u = 0; u < 4; u++) {
                int idx = t + 512 * u;
                int o4 = (idx & 31) * 4;
                int k  = idx >> 5;
                *(float4*)&sB[k * 132 + o4] = *(const float4*)(g_VW + ((size_t)(h * Nn + kb + k)) * DNn + o4);
            }
        } else {
            #pragma unroll
            for (int u = 0; u < 4; u++) {
                int idx = t + 512 * u;
                int k4 = (idx & 15) * 4;
                int i  = idx >> 4;
                *(float4*)&sA[i * 68 + k4] =
                    *(const float4*)(g_ew + (size_t)h * (Nn * DEn) + (size_t)(i0 + i) * DEn + k4);
            }
            #pragma unroll
            for (int u = 0; u < 4; u++) {
                int idx = t + 512 * u;
                int o4 = (idx & 31) * 4;
                int k  = idx >> 5;
                *(float4*)&sB[k * 132 + o4] = *(const float4*)(g_M + ((size_t)(h * 64 + k)) * DNn + o4);
            }
        }
        __syncthreads();

        #pragma unroll 4
        for (int k = 0; k < 64; k++) {
            ulonglong2 bv = *(const ulonglong2*)&sB[k * 132 + ob];
            #pragma unroll
            for (int ii = 0; ii < 8; ii++) {
                float a = sA[(ib + ii) * 68 + k];   // warp-uniform -> broadcast
                ull ad = pk2(a, a);
                fma2(acc[ii][0], ad, bv.x);
                fma2(acc[ii][1], ad, bv.y);
            }
        }
        __syncthreads();
    }

    float* pp = g_part + (size_t)blockIdx.y * (Nn * DNn);
    #pragma unroll
    for (int ii = 0; ii < 8; ii++) {
        float2 f0 = upk2(acc[ii][0]);
        float2 f1 = upk2(acc[ii][1]);
        *(float2*)(pp + (size_t)(i0 + ib + ii) * DNn + ob)     = f0;
        *(float2*)(pp + (size_t)(i0 + ib + ii) * DNn + ob + 2) = f1;
    }
}

// ---------------- kernel 6: reduce partials + bvec -> out ----------------
__global__ void __launch_bounds__(256)
reduce_out_kernel(float* __restrict__ out)
{
    const int idx = blockIdx.x * 256 + threadIdx.x;
    float a0 = 0.f, a1 = 0.f, a2 = 0.f, a3 = 0.f;
    #pragma unroll
    for (int s = 0; s < 32; s += 4) {
        a0 += g_part[(size_t)s       * (Nn * DNn) + idx];
        a1 += g_part[(size_t)(s + 1) * (Nn * DNn) + idx];
        a2 += g_part[(size_t)(s + 2) * (Nn * DNn) + idx];
        a3 += g_part[(size_t)(s + 3) * (Nn * DNn) + idx];
    }
    out[idx] = (a0 + a1) + (a2 + a3) + g_bvec[idx & 127];
}

// ---------------- launch ----------------
extern "C" void kernel_launch(void* const* d_in, const int* in_sizes, int n_in,
                              void* d_out, int out_size)
{
    const float* nodes = (const float*)d_in[0];
    const float* edges = (const float*)d_in[1];
    const float* Wq = (const float*)d_in[3];
    const float* bq = (const float*)d_in[4];
    const float* Wk = (const float*)d_in[5];
    const float* bk = (const float*)d_in[6];
    const float* Wv = (const float*)d_in[7];
    const float* bv = (const float*)d_in[8];
    const float* We = (const float*)d_in[9];
    const float* be = (const float*)d_in[10];
    const float* Wo = (const float*)d_in[11];
    const float* bo = (const float*)d_in[12];
    float* out = (float*)d_out;

    float* kptr; float* vptr;
    cudaGetSymbolAddress((void**)&kptr, g_k);
    cudaGetSymbolAddress((void**)&vptr, g_v);

    cudaFuncSetAttribute(edge_mega_kernel, cudaFuncAttributeMaxDynamicSharedMemorySize, EM_SMEM);
    cudaFuncSetAttribute(gemm_out_kernel, cudaFuncAttributeMaxDynamicSharedMemorySize, GO_SMEM);

    dim3 g1(16, 24);
    qkv_kernel<<<g1, 256>>>(nodes, Wq, bq, Wk, bk, Wv, bv, We, be);
    wcomb_kernel<<<193, 256>>>(We, be, Wo, bo, vptr);
    qksim_kernel<<<dim3(16, 4, 8), 256>>>(kptr);
    edge_mega_kernel<<<Nn, 256, EM_SMEM>>>(edges);
    gemm_out_kernel<<<dim3(4, 32), 512, GO_SMEM>>>();
    reduce_out_kernel<<<(Nn * DNn) / 256, 256>>>(out);
}